// round 3
// baseline (speedup 1.0000x reference)
#include <cuda_runtime.h>
#include <math.h>

#define HD 512
#define ND 512
#define BS 8
#define LS 4096
#define NHALF 256
#define NCH 32
#define CHL 128

// Scratch: Bu (then x) in [b][n][l] float2 layout. 134 MB.
__device__ float2 g_bu[(size_t)BS * ND * LS];
__device__ float2 g_carry[BS * NCH * ND];
__device__ float2 g_cin[BS * NCH * ND];

__device__ __forceinline__ void lam_of(int n, const float* __restrict__ nu_log,
                                       const float* __restrict__ th_log,
                                       float& lr, float& li) {
    float nu  = expf(nu_log[n]);
    float mag = expf(-nu);
    float th  = expf(th_log[n]);
    float s, c;
    sincosf(th, &s, &c);
    lr = mag * c;
    li = mag * s;
}

// ---------------- GEMM1: Bu[b][n][l] = mask * (u @ Bc) ----------------
// A: u (B,L,H) fp32. W: B (H,N,2) -> complex weights. Output: g_bu float2.
__global__ __launch_bounds__(256)
void gemm_bu(const float* __restrict__ u, const float* __restrict__ Bw,
             const int* __restrict__ lengths) {
    __shared__ float  As[16][132];   // [k][m], padded
    __shared__ float2 Ws[16][64];    // [k][n] complex

    int tid = threadIdx.x;
    int tx = tid & 15, ty = tid >> 4;
    int n0 = blockIdx.x * 64;
    int b  = blockIdx.y >> 5;              // 32 blocks per batch (4096/128)
    int l0 = (blockIdx.y & 31) * 128;

    const float* ub = u + ((size_t)b * LS + l0) * HD;

    float accr[8][4] = {};
    float acci[8][4] = {};

    for (int k0 = 0; k0 < HD; k0 += 16) {
        // Load A tile: 128 rows x 16 k = 512 float4
#pragma unroll
        for (int j = 0; j < 2; j++) {
            int idx = tid + 256 * j;
            int row = idx >> 2, kq = idx & 3;
            float4 f = *(const float4*)(ub + (size_t)row * HD + k0 + kq * 4);
            As[kq * 4 + 0][row] = f.x;
            As[kq * 4 + 1][row] = f.y;
            As[kq * 4 + 2][row] = f.z;
            As[kq * 4 + 3][row] = f.w;
        }
        // Load W tile: 16 k x 64 n float2
#pragma unroll
        for (int j = 0; j < 4; j++) {
            int idx = tid + 256 * j;
            int kr = idx >> 6, nc = idx & 63;
            Ws[kr][nc] = *(const float2*)(Bw + 2 * ((size_t)(k0 + kr) * ND + n0 + nc));
        }
        __syncthreads();

#pragma unroll
        for (int kk = 0; kk < 16; kk++) {
            float a[8];
            float4 a0 = *(const float4*)&As[kk][ty * 8];
            float4 a1 = *(const float4*)&As[kk][ty * 8 + 4];
            a[0] = a0.x; a[1] = a0.y; a[2] = a0.z; a[3] = a0.w;
            a[4] = a1.x; a[5] = a1.y; a[6] = a1.z; a[7] = a1.w;
            float4 w0 = *(const float4*)&Ws[kk][tx * 4];       // 2 complexes
            float4 w1 = *(const float4*)&Ws[kk][tx * 4 + 2];   // 2 complexes
            float wr[4] = {w0.x, w0.z, w1.x, w1.z};
            float wi[4] = {w0.y, w0.w, w1.y, w1.w};
#pragma unroll
            for (int i = 0; i < 8; i++)
#pragma unroll
                for (int j = 0; j < 4; j++) {
                    accr[i][j] = fmaf(a[i], wr[j], accr[i][j]);
                    acci[i][j] = fmaf(a[i], wi[j], acci[i][j]);
                }
        }
        __syncthreads();
    }

    int len = lengths[b];
#pragma unroll
    for (int j = 0; j < 4; j++) {
        int n = n0 + tx * 4 + j;
        float2* dst = &g_bu[((size_t)(b * ND + n)) * LS + l0 + ty * 8];
#pragma unroll
        for (int ii = 0; ii < 4; ii++) {
            int l = l0 + ty * 8 + ii * 2;
            float4 v;
            if (l < len)     { v.x = accr[ii * 2][j];     v.y = acci[ii * 2][j]; }
            else             { v.x = 0.f; v.y = 0.f; }
            if (l + 1 < len) { v.z = accr[ii * 2 + 1][j]; v.w = acci[ii * 2 + 1][j]; }
            else             { v.z = 0.f; v.w = 0.f; }
            *(float4*)(dst + ii * 2) = v;
        }
    }
}

// ---------------- Scan phase A: per-chunk local scan (warp per (b,n,chunk)) ---
// Logical coordinate t: forward channels t == l; reverse channels t == L-1-l.
__global__ __launch_bounds__(256)
void scanA(const float* __restrict__ nu_log, const float* __restrict__ th_log) {
    int gw   = (blockIdx.x * 256 + threadIdx.x) >> 5;
    int lane = threadIdx.x & 31;
    int chunk = gw & (NCH - 1);
    int n     = (gw >> 5) & (ND - 1);
    int b     = gw >> 14;

    float lr, li;
    lam_of(n, nu_log, th_log, lr, li);
    bool rev = (n >= NHALF);

    float2* base = g_bu + ((size_t)(b * ND + n)) * LS;
    int t0 = chunk * CHL + lane * 4;
    int pb = LS - 4 - t0;  // lowest physical index for reverse

    float cr[4], ci[4];
    if (!rev) {
        float4 f0 = *(const float4*)(base + t0);
        float4 f1 = *(const float4*)(base + t0 + 2);
        cr[0] = f0.x; ci[0] = f0.y; cr[1] = f0.z; ci[1] = f0.w;
        cr[2] = f1.x; ci[2] = f1.y; cr[3] = f1.z; ci[3] = f1.w;
    } else {
        float4 f0 = *(const float4*)(base + pb);      // physical pb, pb+1
        float4 f1 = *(const float4*)(base + pb + 2);  // physical pb+2, pb+3
        // logical t0+i <-> physical (pb+3)-i
        cr[0] = f1.z; ci[0] = f1.w; cr[1] = f1.x; ci[1] = f1.y;
        cr[2] = f0.z; ci[2] = f0.w; cr[3] = f0.x; ci[3] = f0.y;
    }

    // Lane-local scan (seed 0)
    float yr[4], yi[4];
    yr[0] = cr[0]; yi[0] = ci[0];
#pragma unroll
    for (int i = 1; i < 4; i++) {
        yr[i] = fmaf(lr, yr[i - 1], fmaf(-li, yi[i - 1], cr[i]));
        yi[i] = fmaf(lr, yi[i - 1], fmaf( li, yr[i - 1], ci[i]));
    }

    // lam^4
    float l2r = lr * lr - li * li, l2i = 2.f * lr * li;
    float fr  = l2r * l2r - l2i * l2i, fi = 2.f * l2r * l2i;

    // Warp inclusive scan of lane-final states with factors lam^(4*2^s)
    float sr = yr[3], si = yi[3];
#pragma unroll
    for (int s = 1; s < 32; s <<= 1) {
        float pr_ = __shfl_up_sync(0xffffffffu, sr, s);
        float pi_ = __shfl_up_sync(0xffffffffu, si, s);
        if (lane >= s) {
            sr = fmaf(fr, pr_, fmaf(-fi, pi_, sr));
            si = fmaf(fr, pi_, fmaf( fi, pr_, si));
        }
        float nfr = fr * fr - fi * fi;
        fi = 2.f * fr * fi;
        fr = nfr;
    }
    float car = __shfl_up_sync(0xffffffffu, sr, 1);
    float cai = __shfl_up_sync(0xffffffffu, si, 1);
    if (lane == 0) { car = 0.f; cai = 0.f; }

    // Fix up own 4 with exclusive carry: x_i = y_i + lam^(i+1)*carry
    float pr = lr, pi = li;
    float xr[4], xi[4];
#pragma unroll
    for (int i = 0; i < 4; i++) {
        xr[i] = yr[i] + pr * car - pi * cai;
        xi[i] = yi[i] + pr * cai + pi * car;
        float t = pr * lr - pi * li;
        pi = pr * li + pi * lr;
        pr = t;
    }

    if (lane == 31) g_carry[(b * NCH + chunk) * ND + n] = make_float2(sr, si);

    if (!rev) {
        *(float4*)(base + t0)     = make_float4(xr[0], xi[0], xr[1], xi[1]);
        *(float4*)(base + t0 + 2) = make_float4(xr[2], xi[2], xr[3], xi[3]);
    } else {
        *(float4*)(base + pb)     = make_float4(xr[3], xi[3], xr[2], xi[2]);
        *(float4*)(base + pb + 2) = make_float4(xr[1], xi[1], xr[0], xi[0]);
    }
}

// ---------------- Scan phase B: inter-chunk carry scan (logical order) -------
__global__ void scanB(const float* __restrict__ nu_log, const float* __restrict__ th_log) {
    int t = blockIdx.x * blockDim.x + threadIdx.x;  // 0..4095
    int n = t & (ND - 1);
    int b = t >> 9;

    float lr, li;
    lam_of(n, nu_log, th_log, lr, li);
    // lam^128 via 7 squarings
    float ar = lr, ai = li;
#pragma unroll
    for (int s = 0; s < 7; s++) {
        float t2 = ar * ar - ai * ai;
        ai = 2.f * ar * ai;
        ar = t2;
    }

    float pr = 0.f, pi = 0.f;
    for (int c = 0; c < NCH; c++) {
        int idx = (b * NCH + c) * ND + n;
        g_cin[idx] = make_float2(pr, pi);
        float2 s2 = g_carry[idx];
        float t2 = fmaf(ar, pr, fmaf(-ai, pi, s2.x));
        pi = fmaf(ar, pi, fmaf(ai, pr, s2.y));
        pr = t2;
    }
}

// ---------------- Scan phase C: apply chunk carries + length masking ---------
__global__ __launch_bounds__(256)
void scanC(const int* __restrict__ lengths, const float* __restrict__ nu_log,
           const float* __restrict__ th_log) {
    int gw   = (blockIdx.x * 256 + threadIdx.x) >> 5;
    int lane = threadIdx.x & 31;
    int chunk = gw & (NCH - 1);
    int n     = (gw >> 5) & (ND - 1);
    int b     = gw >> 14;

    float lr, li;
    lam_of(n, nu_log, th_log, lr, li);
    bool rev = (n >= NHALF);
    int len = lengths[b];

    float2* base = g_bu + ((size_t)(b * ND + n)) * LS;
    int t0 = chunk * CHL + lane * 4;
    int pb = LS - 4 - t0;

    float xr[4], xi[4];
    if (!rev) {
        float4 f0 = *(const float4*)(base + t0);
        float4 f1 = *(const float4*)(base + t0 + 2);
        xr[0] = f0.x; xi[0] = f0.y; xr[1] = f0.z; xi[1] = f0.w;
        xr[2] = f1.x; xi[2] = f1.y; xr[3] = f1.z; xi[3] = f1.w;
    } else {
        float4 f0 = *(const float4*)(base + pb);
        float4 f1 = *(const float4*)(base + pb + 2);
        xr[0] = f1.z; xi[0] = f1.w; xr[1] = f1.x; xi[1] = f1.y;
        xr[2] = f0.z; xi[2] = f0.w; xr[3] = f0.x; xi[3] = f0.y;
    }

    float2 C = g_cin[(b * NCH + chunk) * ND + n];

    // lam^4
    float l2r = lr * lr - li * li, l2i = 2.f * lr * li;
    float f4r = l2r * l2r - l2i * l2i, f4i = 2.f * l2r * l2i;
    // p = (lam^4)^lane via exponent bits
    float p4r = 1.f, p4i = 0.f, qr = f4r, qi = f4i;
#pragma unroll
    for (int bit = 0; bit < 5; bit++) {
        if (lane & (1 << bit)) {
            float t2 = p4r * qr - p4i * qi;
            p4i = p4r * qi + p4i * qr;
            p4r = t2;
        }
        float t3 = qr * qr - qi * qi;
        qi = 2.f * qr * qi;
        qr = t3;
    }
    // pw = lam^(4*lane + 1)
    float pwr = p4r * lr - p4i * li;
    float pwi = p4r * li + p4i * lr;

#pragma unroll
    for (int i = 0; i < 4; i++) {
        xr[i] += pwr * C.x - pwi * C.y;
        xi[i] += pwr * C.y + pwi * C.x;
        float t2 = pwr * lr - pwi * li;
        pwi = pwr * li + pwi * lr;
        pwr = t2;
        int l = rev ? (LS - 1 - (t0 + i)) : (t0 + i);
        if (l >= len) { xr[i] = 0.f; xi[i] = 0.f; }
    }

    if (!rev) {
        *(float4*)(base + t0)     = make_float4(xr[0], xi[0], xr[1], xi[1]);
        *(float4*)(base + t0 + 2) = make_float4(xr[2], xi[2], xr[3], xi[3]);
    } else {
        *(float4*)(base + pb)     = make_float4(xr[3], xi[3], xr[2], xi[2]);
        *(float4*)(base + pb + 2) = make_float4(xr[1], xi[1], xr[0], xi[0]);
    }
}

// ---------------- GEMM2: y[b][l][j] = xr@C0 - xi@C1 ----------------
__global__ __launch_bounds__(256)
void gemm_y(const float* __restrict__ Cw, float* __restrict__ out) {
    __shared__ float2 Xs[8][128];   // [k][l] complex
    __shared__ float  W0[8][128];
    __shared__ float  W1[8][128];

    int tid = threadIdx.x;
    int tx = tid & 15, ty = tid >> 4;
    int j0 = blockIdx.x * 128;
    int b  = blockIdx.y >> 5;
    int l0 = (blockIdx.y & 31) * 128;

    const float* C0 = Cw;
    const float* C1 = Cw + (size_t)HD * ND;

    float acc[8][8] = {};

    for (int k0 = 0; k0 < ND; k0 += 8) {
        // X tile: 8 k x 128 l float2 = 512 float4
#pragma unroll
        for (int j = 0; j < 2; j++) {
            int idx = tid + 256 * j;
            int kr = idx >> 6, lc = (idx & 63) * 2;
            float4 f = *(const float4*)(g_bu + ((size_t)(b * ND + k0 + kr)) * LS + l0 + lc);
            *(float4*)&Xs[kr][lc] = f;
        }
        // W tiles: 8 k x 128 j floats each
        {
            int kr = tid >> 5, jc = (tid & 31) * 4;
            *(float4*)&W0[kr][jc] = *(const float4*)(C0 + (size_t)(k0 + kr) * ND + j0 + jc);
            *(float4*)&W1[kr][jc] = *(const float4*)(C1 + (size_t)(k0 + kr) * ND + j0 + jc);
        }
        __syncthreads();

#pragma unroll
        for (int kk = 0; kk < 8; kk++) {
            float ar[8], nai[8];
#pragma unroll
            for (int q = 0; q < 4; q++) {
                float4 f = *(const float4*)&Xs[kk][ty * 8 + q * 2];
                ar[q * 2]     = f.x;  nai[q * 2]     = -f.y;
                ar[q * 2 + 1] = f.z;  nai[q * 2 + 1] = -f.w;
            }
            float w0[8], w1[8];
            float4 u0 = *(const float4*)&W0[kk][tx * 8];
            float4 u1 = *(const float4*)&W0[kk][tx * 8 + 4];
            w0[0] = u0.x; w0[1] = u0.y; w0[2] = u0.z; w0[3] = u0.w;
            w0[4] = u1.x; w0[5] = u1.y; w0[6] = u1.z; w0[7] = u1.w;
            float4 v0 = *(const float4*)&W1[kk][tx * 8];
            float4 v1 = *(const float4*)&W1[kk][tx * 8 + 4];
            w1[0] = v0.x; w1[1] = v0.y; w1[2] = v0.z; w1[3] = v0.w;
            w1[4] = v1.x; w1[5] = v1.y; w1[6] = v1.z; w1[7] = v1.w;
#pragma unroll
            for (int i = 0; i < 8; i++)
#pragma unroll
                for (int j = 0; j < 8; j++) {
                    acc[i][j] = fmaf(ar[i],  w0[j], acc[i][j]);
                    acc[i][j] = fmaf(nai[i], w1[j], acc[i][j]);
                }
        }
        __syncthreads();
    }

    float* ob = out + ((size_t)b * LS + l0) * HD + j0;
#pragma unroll
    for (int i = 0; i < 8; i++) {
        *(float4*)&ob[(size_t)(ty * 8 + i) * HD + tx * 8] =
            make_float4(acc[i][0], acc[i][1], acc[i][2], acc[i][3]);
        *(float4*)&ob[(size_t)(ty * 8 + i) * HD + tx * 8 + 4] =
            make_float4(acc[i][4], acc[i][5], acc[i][6], acc[i][7]);
    }
}

extern "C" void kernel_launch(void* const* d_in, const int* in_sizes, int n_in,
                              void* d_out, int out_size) {
    const float* u         = (const float*)d_in[0];
    const int*   lengths   = (const int*)d_in[1];
    const float* nu_log    = (const float*)d_in[2];
    const float* theta_log = (const float*)d_in[3];
    const float* Bw        = (const float*)d_in[4];
    const float* Cw        = (const float*)d_in[5];
    float* out = (float*)d_out;

    dim3 g1(ND / 64, (BS * LS) / 128);   // (8, 256)
    gemm_bu<<<g1, 256>>>(u, Bw, lengths);

    // 131072 warps total: one per (b, n, chunk); 8 warps per block
    scanA<<<16384, 256>>>(nu_log, theta_log);
    scanB<<<16, 256>>>(nu_log, theta_log);
    scanC<<<16384, 256>>>(lengths, nu_log, theta_log);

    dim3 g2(HD / 128, (BS * LS) / 128);  // (4, 256)
    gemm_y<<<g2, 256>>>(Cw, out);
}